// round 16
// baseline (speedup 1.0000x reference)
#include <cuda_runtime.h>
#include <cuda_fp16.h>
#include <cstdint>
#include <math.h>

#define EMBED 768
#define BQ    256
#define NTOT  16384
#define SCALE 0.1020620726159657f   // 96^-0.5

#define NPROJ 1560       // (2 Q m-blocks + 128 K m-blocks) x 12 n-tiles of 64
#define NATTN 2048       // 4 b-blocks(64) x 512 n-blocks(32)
#define NTICK (NPROJ + NATTN)

// ---------------------------------------------------------------------------
// Device scratch (static globals — no runtime allocation)
// ---------------------------------------------------------------------------
__device__ __half g_sh_hi[NTOT*EMBED];                          // search hi
__device__ __half g_qi_hi[BQ*EMBED];                            // query hi
__device__ __half g_wk_hi[EMBED*EMBED];                         // Wk hi
__device__ __half g_wq_hi[EMBED*EMBED];                         // Wq hi
__device__ __half g_k_hi[NTOT*EMBED];                           // projected K hi
__device__ __half g_qp_hi[BQ*EMBED];                            // projected Q hi

__device__ int g_ticket;
__device__ int g_kdone[128];   // per K m-block: n-tiles done (-> 12)
__device__ int g_qdone[2];     // per Q m-block: n-tiles done (-> 12)

// ---------------------------------------------------------------------------
// Helpers
// ---------------------------------------------------------------------------
__device__ __forceinline__ uint32_t smem_u32(const void* p) {
    uint32_t a;
    asm("{ .reg .u64 t; cvta.to.shared.u64 t, %1; cvt.u32.u64 %0, t; }"
        : "=r"(a) : "l"(p));
    return a;
}

__device__ __forceinline__ void cp16(uint32_t dst, const void* src) {
    asm volatile("cp.async.cg.shared.global [%0], [%1], 16;" :: "r"(dst), "l"(src));
}
#define CP_COMMIT() asm volatile("cp.async.commit_group;")
#define CP_WAIT0()  asm volatile("cp.async.wait_group 0;")

__device__ __forceinline__ void ldm_x4(uint32_t& r0, uint32_t& r1, uint32_t& r2,
                                       uint32_t& r3, uint32_t addr) {
    asm volatile("ldmatrix.sync.aligned.m8n8.x4.shared.b16 {%0,%1,%2,%3}, [%4];"
                 : "=r"(r0), "=r"(r1), "=r"(r2), "=r"(r3) : "r"(addr));
}

__device__ __forceinline__ void ldm_x2(uint32_t& r0, uint32_t& r1, uint32_t addr) {
    asm volatile("ldmatrix.sync.aligned.m8n8.x2.shared.b16 {%0,%1}, [%2];"
                 : "=r"(r0), "=r"(r1) : "r"(addr));
}

__device__ __forceinline__ void mma_f16(float c[4], uint32_t a0, uint32_t a1,
                                        uint32_t a2, uint32_t a3,
                                        uint32_t b0, uint32_t b1) {
    asm volatile(
        "mma.sync.aligned.m16n8k16.row.col.f32.f16.f16.f32 "
        "{%0,%1,%2,%3}, {%4,%5,%6,%7}, {%8,%9}, {%0,%1,%2,%3};"
        : "+f"(c[0]), "+f"(c[1]), "+f"(c[2]), "+f"(c[3])
        : "r"(a0), "r"(a1), "r"(a2), "r"(a3), "r"(b0), "r"(b1));
}

// ---------------------------------------------------------------------------
// Fused split: all tensors hi-only.
// ---------------------------------------------------------------------------
#define N4S (NTOT*EMBED/4)
#define N4Q (BQ*EMBED/4)
#define N4W (EMBED*EMBED/4)

__global__ void split_all(const float* __restrict__ search,
                          const float* __restrict__ query,
                          const float* __restrict__ Wk,
                          const float* __restrict__ Wq) {
    if (blockIdx.x == 0) {          // reset queue + flags
        if (threadIdx.x == 0) g_ticket = 0;
        if (threadIdx.x < 128) g_kdone[threadIdx.x] = 0;
        if (threadIdx.x < 2)   g_qdone[threadIdx.x] = 0;
    }
    int i = blockIdx.x * blockDim.x + threadIdx.x;
    const float* src;
    __half* hi;
    if (i < N4S)                      { src = search; hi = g_sh_hi; }
    else if ((i -= N4S) < N4Q)        { src = query;  hi = g_qi_hi; }
    else if ((i -= N4Q) < N4W)        { src = Wk;     hi = g_wk_hi; }
    else if ((i -= N4W) < N4W)        { src = Wq;     hi = g_wq_hi; }
    else return;
    float4 v = ((const float4*)src)[i];
    ((__half2*)hi)[i*2]   = __halves2half2(__float2half(v.x), __float2half(v.y));
    ((__half2*)hi)[i*2+1] = __halves2half2(__float2half(v.z), __float2half(v.w));
}

// ---------------------------------------------------------------------------
// Fused persistent kernel, 4 warps/SMSP build: 296 CTAs x 256 threads,
// 2 CTA/SM (16 warps/SM). Regs capped at 128 by launch bounds.
// smem: two 24K buffers @ buf*24576 | w1 @49152 | mlp @49280 | ticket @49408.
// Proj: tile 128x64, warps 4m x 2n, warp 32x32.
// Attn: tile 64x32, warps 2m x 4n, warp 32x8 (B via ldmatrix.x2).
// ---------------------------------------------------------------------------
__global__ __launch_bounds__(256, 2)
void fused_tc(const float* __restrict__ bk, const float* __restrict__ bq,
              const float* __restrict__ W1, const float* __restrict__ b1,
              const float* __restrict__ W2, const float* __restrict__ b2,
              float* __restrict__ outp)
{
    extern __shared__ char dsm[];
    const uint32_t sb = smem_u32(dsm);
    float* s_w1 = (float*)(dsm + 49152);
    float* s_mi = (float*)(dsm + 49280);
    int*   s_tk = (int*)(dsm + 49408);
    const int tid = threadIdx.x, wid = tid >> 5, lane = tid & 31;

    if (tid < 32) s_w1[tid] = W1[tid] * SCALE;
    if (tid < 4)  { s_mi[tid] = b1[tid]; s_mi[4 + tid] = W2[tid]; }
    if (tid == 8) s_mi[8] = b2[0];

    const int g  = lane >> 3;
    const int gr = ((g & 1) << 3) + (lane & 7);   // A-frag row sel
    const int gk = (g >> 1) << 4;                 // A-frag k sel
    const int hr = ((g >> 1) << 3) + (lane & 7);  // B-frag row sel (x4)
    const int hk = (g & 1) << 4;                  // B-frag k sel (x4)

    __syncthreads();

    for (;;) {
        if (tid == 0) *s_tk = atomicAdd(&g_ticket, 1);
        __syncthreads();
        const int t = *s_tk;
        if (t >= NTICK) break;

        if (t < NPROJ) {
            // ============== PROJ TILE 128(m) x 64(n), warp 32x32 ==============
            const int wm = wid & 3, wn = wid >> 2;
            const __half *Ahi;
            __half* Ohi;
            const float* bias;
            int m0, n0;
            if (t < 24) { Ahi = g_qi_hi; Ohi = g_qp_hi; bias = bq;
                          m0 = (t / 12) * 128; n0 = (t % 12) * 64; }
            else        { const int tt = t - 24;
                          Ahi = g_sh_hi; Ohi = g_k_hi; bias = bk;
                          m0 = (tt / 12) * 128; n0 = (tt % 12) * 64; }
            const __half* Bhi = (t < 24) ? g_wq_hi : g_wk_hi;

            float c[2][4][4];
#pragma unroll
            for (int i = 0; i < 2; ++i)
#pragma unroll
                for (int j = 0; j < 4; ++j)
#pragma unroll
                    for (int k = 0; k < 4; ++k) c[i][j][k] = 0.0f;

            auto issue = [&](int chunk, int buf) {
                const int k0 = chunk * 64;
                const uint32_t base = sb + (uint32_t)buf * 24576u;
#pragma unroll
                for (int i = 0; i < 4; ++i) {        // A: 1024 segs (128r x 128B)
                    const int seg = tid + 256 * i;
                    const int row = seg >> 3, sg = seg & 7;
                    const uint32_t off = (uint32_t)row * 128u +
                                         ((uint32_t)(sg * 16) ^ (uint32_t)((row & 7) << 4));
                    cp16(base + off, Ahi + (size_t)(m0 + row) * EMBED + k0 + sg * 8);
                }
#pragma unroll
                for (int i = 0; i < 2; ++i) {        // B: 512 segs (64r x 128B)
                    const int seg = tid + 256 * i;
                    const int row = seg >> 3, sg = seg & 7;
                    const uint32_t off = (uint32_t)row * 128u +
                                         ((uint32_t)(sg * 16) ^ (uint32_t)((row & 7) << 4));
                    cp16(base + 16384u + off, Bhi + (size_t)(n0 + row) * EMBED + k0 + sg * 8);
                }
                CP_COMMIT();
            };

            issue(0, 0);

#pragma unroll 1
            for (int ch = 0; ch < 12; ++ch) {
                CP_WAIT0();
                __syncthreads();
                const int b = ch & 1;
                if (ch + 1 < 12) issue(ch + 1, b ^ 1);

                const uint32_t Ab = sb + (uint32_t)b * 24576u;
                const uint32_t Bb = Ab + 16384u;
#pragma unroll
                for (int ks = 0; ks < 4; ++ks) {
                    uint32_t bf[4][2];
#pragma unroll
                    for (int p = 0; p < 2; ++p) {
                        const int r = wn * 32 + p * 16 + hr;
                        const int kb = ks * 32 + hk;
                        uint32_t r0, r1, r2, r3;
                        ldm_x4(r0, r1, r2, r3,
                               Bb + (uint32_t)r * 128u + (uint32_t)(kb ^ ((r & 7) << 4)));
                        bf[2*p][0] = r0;   bf[2*p][1] = r1;
                        bf[2*p+1][0] = r2; bf[2*p+1][1] = r3;
                    }
                    uint32_t a[2][4];
#pragma unroll
                    for (int mt = 0; mt < 2; ++mt) {
                        const int r = wm * 32 + mt * 16 + gr;
                        const int kb = ks * 32 + gk;
                        ldm_x4(a[mt][0], a[mt][1], a[mt][2], a[mt][3],
                               Ab + (uint32_t)r * 128u + (uint32_t)(kb ^ ((r & 7) << 4)));
                    }
#pragma unroll
                    for (int mt = 0; mt < 2; ++mt)
#pragma unroll
                        for (int nt = 0; nt < 4; ++nt)
                            mma_f16(c[mt][nt], a[mt][0], a[mt][1], a[mt][2], a[mt][3],
                                    bf[nt][0], bf[nt][1]);
                }
            }

            // Epilogue: bias + fp16 hi store
#pragma unroll
            for (int mt = 0; mt < 2; ++mt) {
#pragma unroll
                for (int nt = 0; nt < 4; ++nt) {
                    const int col = n0 + wn * 32 + nt * 8 + (lane & 3) * 2;
                    const float bc0 = __ldg(bias + col), bc1 = __ldg(bias + col + 1);
#pragma unroll
                    for (int h = 0; h < 2; ++h) {
                        const int row = m0 + wm * 32 + mt * 16 + (lane >> 2) + h * 8;
                        float x0 = c[mt][nt][2*h]   + bc0;
                        float x1 = c[mt][nt][2*h+1] + bc1;
                        *(__half2*)(Ohi + (size_t)row * EMBED + col) =
                            __halves2half2(__float2half(x0), __float2half(x1));
                    }
                }
            }

            // publish
            __syncthreads();
            if (tid == 0) {
                __threadfence();
                if (t < 24) atomicAdd(&g_qdone[t / 12], 1);
                else        atomicAdd(&g_kdone[(t - 24) / 12], 1);
            }
        } else {
            // ============== ATTN TILE 64(b) x 32(n), warp 32x8 ================
            const int wm = wid & 1, wn = wid >> 1;   // 2m x 4n
            const int u  = t - NPROJ;
            const int bb = u & 3, nb = u >> 2;
            const int m0 = bb * 64, n0 = nb * 32;

            if (tid == 0) {
                while (atomicAdd(&g_kdone[nb >> 2], 0) < 12) __nanosleep(64);
                while (atomicAdd(&g_qdone[bb >> 1], 0) < 12) __nanosleep(64);
            }
            __syncthreads();

            float c[2][4];
            float hp[2][4][4];
#pragma unroll
            for (int i = 0; i < 2; ++i)
#pragma unroll
                for (int k = 0; k < 4; ++k) {
                    c[i][k] = 0.0f;
#pragma unroll
                    for (int l = 0; l < 4; ++l) hp[i][k][l] = 0.0f;
                }

            auto issue = [&](int chunk, int buf) {
                const int k0 = chunk * 128;
                const uint32_t base = sb + (uint32_t)buf * 24576u;
#pragma unroll
                for (int i = 0; i < 4; ++i) {        // Q: 1024 segs (64r x 256B)
                    const int seg = tid + 256 * i;
                    const int row = seg >> 4, sg = seg & 15;
                    const uint32_t off = (uint32_t)row * 256u +
                                         ((uint32_t)(sg * 16) ^ (uint32_t)((row & 15) << 4));
                    cp16(base + off, g_qp_hi + (size_t)(m0 + row) * EMBED + k0 + sg * 8);
                }
#pragma unroll
                for (int i = 0; i < 2; ++i) {        // K: 512 segs (32r x 256B)
                    const int seg = tid + 256 * i;
                    const int row = seg >> 4, sg = seg & 15;
                    const uint32_t off = (uint32_t)row * 256u +
                                         ((uint32_t)(sg * 16) ^ (uint32_t)((row & 15) << 4));
                    cp16(base + 16384u + off, g_k_hi + (size_t)(n0 + row) * EMBED + k0 + sg * 8);
                }
                CP_COMMIT();
            };

            issue(0, 0);

            // x2 B-frag addressing: lanes 0-15 give 8 rows x two k-halves
            const int xr = lane & 7;               // row within 8
            const int xk = ((lane >> 3) & 1) << 4; // 0 or 16 bytes

#pragma unroll 1
            for (int ch = 0; ch < 6; ++ch) {
                CP_WAIT0();
                __syncthreads();
                const int b = ch & 1;
                if (ch + 1 < 6) issue(ch + 1, b ^ 1);

                const uint32_t Ab = sb + (uint32_t)b * 24576u;
                const uint32_t Bb = Ab + 16384u;
#pragma unroll
                for (int ks = 0; ks < 8; ++ks) {
                    uint32_t b0, b1;
                    {
                        const int r = wn * 8 + xr;
                        const int kb = ks * 32 + xk;
                        ldm_x2(b0, b1,
                               Bb + (uint32_t)r * 256u + (uint32_t)(kb ^ ((r & 15) << 4)));
                    }
                    uint32_t a[2][4];
#pragma unroll
                    for (int mt = 0; mt < 2; ++mt) {
                        const int r = wm * 32 + mt * 16 + gr;
                        const int kb = ks * 32 + gk;
                        ldm_x4(a[mt][0], a[mt][1], a[mt][2], a[mt][3],
                               Ab + (uint32_t)r * 256u + (uint32_t)(kb ^ ((r & 15) << 4)));
                    }
#pragma unroll
                    for (int mt = 0; mt < 2; ++mt)
                        mma_f16(c[mt], a[mt][0], a[mt][1], a[mt][2], a[mt][3], b0, b1);

                    const int s = ch * 8 + ks;
                    if ((s % 6) == 5) {           // head boundary: fold into hp
                        const int h = s / 6;
                        const float w0 = s_w1[h],       w1v = s_w1[8 + h];
                        const float w2v = s_w1[16 + h], w3  = s_w1[24 + h];
#pragma unroll
                        for (int mt = 0; mt < 2; ++mt)
#pragma unroll
                            for (int k = 0; k < 4; ++k) {
                                const float vv = c[mt][k];
                                hp[mt][k][0] = fmaf(w0,  vv, hp[mt][k][0]);
                                hp[mt][k][1] = fmaf(w1v, vv, hp[mt][k][1]);
                                hp[mt][k][2] = fmaf(w2v, vv, hp[mt][k][2]);
                                hp[mt][k][3] = fmaf(w3,  vv, hp[mt][k][3]);
                                c[mt][k] = 0.0f;
                            }
                    }
                }
            }

            // Epilogue: GELU(erf) + W2, float2 stores
            const float b10 = s_mi[0], b11 = s_mi[1], b12 = s_mi[2], b13 = s_mi[3];
            const float w20 = s_mi[4], w21 = s_mi[5], w22 = s_mi[6], w23 = s_mi[7];
            const float bb2 = s_mi[8];
            const float inv_sqrt2 = 0.70710678118654752f;
#pragma unroll
            for (int mt = 0; mt < 2; ++mt) {
                const int col = n0 + wn * 8 + (lane & 3) * 2;
#pragma unroll
                for (int h = 0; h < 2; ++h) {
                    const int row = m0 + wm * 32 + mt * 16 + (lane >> 2) + h * 8;
                    float o[2];
#pragma unroll
                    for (int e = 0; e < 2; ++e) {
                        const int k = 2 * h + e;
                        float x0 = hp[mt][k][0] + b10;
                        float x1 = hp[mt][k][1] + b11;
                        float x2 = hp[mt][k][2] + b12;
                        float x3 = hp[mt][k][3] + b13;
                        float g0 = 0.5f * x0 * (1.0f + erff(x0 * inv_sqrt2));
                        float g1 = 0.5f * x1 * (1.0f + erff(x1 * inv_sqrt2));
                        float g2 = 0.5f * x2 * (1.0f + erff(x2 * inv_sqrt2));
                        float g3 = 0.5f * x3 * (1.0f + erff(x3 * inv_sqrt2));
                        float s = bb2;
                        s = fmaf(w20, g0, s); s = fmaf(w21, g1, s);
                        s = fmaf(w22, g2, s); s = fmaf(w23, g3, s);
                        o[e] = s;
                    }
                    *(float2*)(outp + (size_t)row * NTOT + col) = make_float2(o[0], o[1]);
                }
            }
        }
    }
}

// ---------------------------------------------------------------------------
extern "C" void kernel_launch(void* const* d_in, const int* in_sizes, int n_in,
                              void* d_out, int out_size)
{
    const float* query  = (const float*)d_in[0];
    const float* search = (const float*)d_in[1];
    const float* Wq     = (const float*)d_in[2];
    const float* bq     = (const float*)d_in[3];
    const float* Wk     = (const float*)d_in[4];
    const float* bk     = (const float*)d_in[5];
    const float* W1     = (const float*)d_in[6];
    const float* b1     = (const float*)d_in[7];
    const float* W2     = (const float*)d_in[8];
    const float* b2     = (const float*)d_in[9];
    float* out = (float*)d_out;

    cudaFuncSetAttribute(fused_tc, cudaFuncAttributeMaxDynamicSharedMemorySize, 49536);

    const int total4 = N4S + N4Q + 2 * N4W;
    split_all<<<(total4 + 255) / 256, 256>>>(search, query, Wk, Wq);

    fused_tc<<<296, 256, 49536>>>(bk, bq, W1, b1, W2, b2, out);
}

// round 17
// speedup vs baseline: 1.1526x; 1.1526x over previous
#include <cuda_runtime.h>
#include <cuda_fp16.h>
#include <cstdint>
#include <math.h>

#define EMBED 768
#define BQ    256
#define NTOT  16384
#define SCALE 0.1020620726159657f   // 96^-0.5

#define NPROJ 1560       // (2 Q m-blocks + 128 K m-blocks) x 12 n-tiles of 64
#define NATTN 2048       // 4 b-blocks(64) x 512 n-blocks(32)
#define NTICK (NPROJ + NATTN)

// ---------------------------------------------------------------------------
// Device scratch (static globals — no runtime allocation)
// ---------------------------------------------------------------------------
__device__ __half g_sh_hi[NTOT*EMBED];                          // search hi
__device__ __half g_qi_hi[BQ*EMBED];                            // query hi
__device__ __half g_wk_hi[EMBED*EMBED];                         // Wk hi
__device__ __half g_wq_hi[EMBED*EMBED];                         // Wq hi
__device__ __half g_k_hi[NTOT*EMBED];                           // projected K hi
__device__ __half g_qp_hi[BQ*EMBED];                            // projected Q hi

__device__ int g_ticket;
__device__ int g_kdone[128];   // per K m-block: n-tiles done (-> 12)
__device__ int g_qdone[2];     // per Q m-block: n-tiles done (-> 12)

// ---------------------------------------------------------------------------
// Helpers
// ---------------------------------------------------------------------------
__device__ __forceinline__ uint32_t smem_u32(const void* p) {
    uint32_t a;
    asm("{ .reg .u64 t; cvta.to.shared.u64 t, %1; cvt.u32.u64 %0, t; }"
        : "=r"(a) : "l"(p));
    return a;
}

__device__ __forceinline__ void cp16(uint32_t dst, const void* src) {
    asm volatile("cp.async.cg.shared.global [%0], [%1], 16;" :: "r"(dst), "l"(src));
}
#define CP_COMMIT() asm volatile("cp.async.commit_group;")
#define CP_WAIT0()  asm volatile("cp.async.wait_group 0;")

// PDL: primary signals dependents may launch; secondary waits for visibility.
#define PDL_TRIGGER() asm volatile("griddepcontrol.launch_dependents;")
#define PDL_WAIT()    asm volatile("griddepcontrol.wait;")

__device__ __forceinline__ void ldm_x4(uint32_t& r0, uint32_t& r1, uint32_t& r2,
                                       uint32_t& r3, uint32_t addr) {
    asm volatile("ldmatrix.sync.aligned.m8n8.x4.shared.b16 {%0,%1,%2,%3}, [%4];"
                 : "=r"(r0), "=r"(r1), "=r"(r2), "=r"(r3) : "r"(addr));
}

__device__ __forceinline__ void mma_f16(float c[4], uint32_t a0, uint32_t a1,
                                        uint32_t a2, uint32_t a3,
                                        uint32_t b0, uint32_t b1) {
    asm volatile(
        "mma.sync.aligned.m16n8k16.row.col.f32.f16.f16.f32 "
        "{%0,%1,%2,%3}, {%4,%5,%6,%7}, {%8,%9}, {%0,%1,%2,%3};"
        : "+f"(c[0]), "+f"(c[1]), "+f"(c[2]), "+f"(c[3])
        : "r"(a0), "r"(a1), "r"(a2), "r"(a3), "r"(b0), "r"(b1));
}

// ---------------------------------------------------------------------------
// Fused split: all tensors hi-only.
// ---------------------------------------------------------------------------
#define N4S (NTOT*EMBED/4)
#define N4Q (BQ*EMBED/4)
#define N4W (EMBED*EMBED/4)

__global__ void split_all(const float* __restrict__ search,
                          const float* __restrict__ query,
                          const float* __restrict__ Wk,
                          const float* __restrict__ Wq) {
    if (blockIdx.x == 0) {          // reset queue + flags
        if (threadIdx.x == 0) g_ticket = 0;
        if (threadIdx.x < 128) g_kdone[threadIdx.x] = 0;
        if (threadIdx.x < 2)   g_qdone[threadIdx.x] = 0;
    }
    int i = blockIdx.x * blockDim.x + threadIdx.x;
    const float* src;
    __half* hi;
    bool work = true;
    if (i < N4S)                      { src = search; hi = g_sh_hi; }
    else if ((i -= N4S) < N4Q)        { src = query;  hi = g_qi_hi; }
    else if ((i -= N4Q) < N4W)        { src = Wk;     hi = g_wk_hi; }
    else if ((i -= N4W) < N4W)        { src = Wq;     hi = g_wq_hi; }
    else work = false;
    if (work) {
        float4 v = ((const float4*)src)[i];
        ((__half2*)hi)[i*2]   = __halves2half2(__float2half(v.x), __float2half(v.y));
        ((__half2*)hi)[i*2+1] = __halves2half2(__float2half(v.z), __float2half(v.w));
    }
    PDL_TRIGGER();   // writes above visible to dependent grid after its wait
}

// ---------------------------------------------------------------------------
// Fused persistent kernel, 3 CTA/SM occupancy build (R15 body).
// 444 CTAs x 128 threads (all resident -> spin-safe).
// smem: two 24K buffers @ buf*24576 (proj A16K+B8K; attn Q16K+K8K)
//       | w1 @49152 | mlp @49280 | ticket @49408.
// Proj tile 128x64 (warp 64x32); attn tile 64x32 (warp 32x16).
// ---------------------------------------------------------------------------
__global__ __launch_bounds__(128, 3)
void fused_tc(const float* __restrict__ bk, const float* __restrict__ bq,
              const float* __restrict__ W1, const float* __restrict__ b1,
              const float* __restrict__ W2, const float* __restrict__ b2,
              float* __restrict__ outp)
{
    extern __shared__ char dsm[];
    const uint32_t sb = smem_u32(dsm);
    float* s_w1 = (float*)(dsm + 49152);
    float* s_mi = (float*)(dsm + 49280);
    int*   s_tk = (int*)(dsm + 49408);
    const int tid = threadIdx.x, wid = tid >> 5, lane = tid & 31;
    const int wm = wid & 1, wn = wid >> 1;

    // Preamble reads ORIGINAL inputs only — legal before the PDL wait.
    if (tid < 32) s_w1[tid] = W1[tid] * SCALE;
    if (tid < 4)  { s_mi[tid] = b1[tid]; s_mi[4 + tid] = W2[tid]; }
    if (tid == 8) s_mi[8] = b2[0];

    const int g  = lane >> 3;
    const int gr = ((g & 1) << 3) + (lane & 7);   // A-frag row sel
    const int gk = (g >> 1) << 4;                 // A-frag k sel
    const int hr = ((g >> 1) << 3) + (lane & 7);  // B-frag row sel
    const int hk = (g & 1) << 4;                  // B-frag k sel

    // Wait for split_all completion (ticket reset + all hi data visible).
    PDL_WAIT();
    __syncthreads();

    for (;;) {
        if (tid == 0) *s_tk = atomicAdd(&g_ticket, 1);
        __syncthreads();
        const int t = *s_tk;
        if (t >= NTICK) break;

        if (t < NPROJ) {
            // ==================== PROJ TILE 128(m) x 64(n), 1-term =============
            const __half *Ahi;
            __half* Ohi;
            const float* bias;
            int m0, n0;
            if (t < 24) { Ahi = g_qi_hi; Ohi = g_qp_hi; bias = bq;
                          m0 = (t / 12) * 128; n0 = (t % 12) * 64; }
            else        { const int tt = t - 24;
                          Ahi = g_sh_hi; Ohi = g_k_hi; bias = bk;
                          m0 = (tt / 12) * 128; n0 = (tt % 12) * 64; }
            const __half* Bhi = (t < 24) ? g_wq_hi : g_wk_hi;

            float c[4][4][4];
#pragma unroll
            for (int i = 0; i < 4; ++i)
#pragma unroll
                for (int j = 0; j < 4; ++j)
#pragma unroll
                    for (int k = 0; k < 4; ++k) c[i][j][k] = 0.0f;

            auto issue = [&](int chunk, int buf) {
                const int k0 = chunk * 64;
                const uint32_t base = sb + (uint32_t)buf * 24576u;
#pragma unroll
                for (int i = 0; i < 8; ++i) {        // A: 1024 segs (128r x 128B)
                    const int seg = tid + 128 * i;
                    const int row = seg >> 3, sg = seg & 7;
                    const uint32_t off = (uint32_t)row * 128u +
                                         ((uint32_t)(sg * 16) ^ (uint32_t)((row & 7) << 4));
                    cp16(base + off, Ahi + (size_t)(m0 + row) * EMBED + k0 + sg * 8);
                }
#pragma unroll
                for (int i = 0; i < 4; ++i) {        // B: 512 segs (64r x 128B)
                    const int seg = tid + 128 * i;
                    const int row = seg >> 3, sg = seg & 7;
                    const uint32_t off = (uint32_t)row * 128u +
                                         ((uint32_t)(sg * 16) ^ (uint32_t)((row & 7) << 4));
                    cp16(base + 16384u + off, Bhi + (size_t)(n0 + row) * EMBED + k0 + sg * 8);
                }
                CP_COMMIT();
            };

            issue(0, 0);

#pragma unroll 1
            for (int ch = 0; ch < 12; ++ch) {
                CP_WAIT0();
                __syncthreads();
                const int b = ch & 1;
                if (ch + 1 < 12) issue(ch + 1, b ^ 1);

                const uint32_t Ab = sb + (uint32_t)b * 24576u;
                const uint32_t Bb = Ab + 16384u;
#pragma unroll
                for (int ks = 0; ks < 4; ++ks) {
                    uint32_t bf[4][2];
#pragma unroll
                    for (int p = 0; p < 2; ++p) {
                        const int r = wn * 32 + p * 16 + hr;
                        const int kb = ks * 32 + hk;
                        uint32_t r0, r1, r2, r3;
                        ldm_x4(r0, r1, r2, r3,
                               Bb + (uint32_t)r * 128u + (uint32_t)(kb ^ ((r & 7) << 4)));
                        bf[2*p][0] = r0;   bf[2*p][1] = r1;
                        bf[2*p+1][0] = r2; bf[2*p+1][1] = r3;
                    }
                    uint32_t a[4][4];
#pragma unroll
                    for (int mt = 0; mt < 4; ++mt) {
                        const int r = wm * 64 + mt * 16 + gr;
                        const int kb = ks * 32 + gk;
                        ldm_x4(a[mt][0], a[mt][1], a[mt][2], a[mt][3],
                               Ab + (uint32_t)r * 128u + (uint32_t)(kb ^ ((r & 7) << 4)));
                    }
#pragma unroll
                    for (int mt = 0; mt < 4; ++mt)
#pragma unroll
                        for (int nt = 0; nt < 4; ++nt)
                            mma_f16(c[mt][nt], a[mt][0], a[mt][1], a[mt][2], a[mt][3],
                                    bf[nt][0], bf[nt][1]);
                }
            }

            // Epilogue: bias + fp16 hi store
#pragma unroll
            for (int mt = 0; mt < 4; ++mt) {
#pragma unroll
                for (int nt = 0; nt < 4; ++nt) {
                    const int col = n0 + wn * 32 + nt * 8 + (lane & 3) * 2;
                    const float bc0 = __ldg(bias + col), bc1 = __ldg(bias + col + 1);
#pragma unroll
                    for (int h = 0; h < 2; ++h) {
                        const int row = m0 + wm * 64 + mt * 16 + (lane >> 2) + h * 8;
                        float x0 = c[mt][nt][2*h]   + bc0;
                        float x1 = c[mt][nt][2*h+1] + bc1;
                        *(__half2*)(Ohi + (size_t)row * EMBED + col) =
                            __halves2half2(__float2half(x0), __float2half(x1));
                    }
                }
            }

            // publish
            __syncthreads();
            if (tid == 0) {
                __threadfence();
                if (t < 24) atomicAdd(&g_qdone[t / 12], 1);
                else        atomicAdd(&g_kdone[(t - 24) / 12], 1);
            }
        } else {
            // ==================== ATTN TILE 64(b) x 32(n) ======================
            const int u  = t - NPROJ;
            const int bb = u & 3, nb = u >> 2;
            const int m0 = bb * 64, n0 = nb * 32;

            if (tid == 0) {
                while (atomicAdd(&g_kdone[nb >> 2], 0) < 12) __nanosleep(64);
                while (atomicAdd(&g_qdone[bb >> 1], 0) < 12) __nanosleep(64);
            }
            __syncthreads();

            float c[2][2][4];
            float hp[2][2][4][4];
#pragma unroll
            for (int i = 0; i < 2; ++i)
#pragma unroll
                for (int j = 0; j < 2; ++j)
#pragma unroll
                    for (int k = 0; k < 4; ++k) {
                        c[i][j][k] = 0.0f;
#pragma unroll
                        for (int l = 0; l < 4; ++l) hp[i][j][k][l] = 0.0f;
                    }

            auto issue = [&](int chunk, int buf) {
                const int k0 = chunk * 128;
                const uint32_t base = sb + (uint32_t)buf * 24576u;
#pragma unroll
                for (int i = 0; i < 8; ++i) {        // Q: 1024 segs (64r x 256B)
                    const int seg = tid + 128 * i;
                    const int row = seg >> 4, sg = seg & 15;
                    const uint32_t off = (uint32_t)row * 256u +
                                         ((uint32_t)(sg * 16) ^ (uint32_t)((row & 15) << 4));
                    cp16(base + off, g_qp_hi + (size_t)(m0 + row) * EMBED + k0 + sg * 8);
                }
#pragma unroll
                for (int i = 0; i < 4; ++i) {        // K: 512 segs (32r x 256B)
                    const int seg = tid + 128 * i;
                    const int row = seg >> 4, sg = seg & 15;
                    const uint32_t off = (uint32_t)row * 256u +
                                         ((uint32_t)(sg * 16) ^ (uint32_t)((row & 15) << 4));
                    cp16(base + 16384u + off, g_k_hi + (size_t)(n0 + row) * EMBED + k0 + sg * 8);
                }
                CP_COMMIT();
            };

            issue(0, 0);

#pragma unroll 1
            for (int ch = 0; ch < 6; ++ch) {
                CP_WAIT0();
                __syncthreads();
                const int b = ch & 1;
                if (ch + 1 < 6) issue(ch + 1, b ^ 1);

                const uint32_t Ab = sb + (uint32_t)b * 24576u;
                const uint32_t Bb = Ab + 16384u;
#pragma unroll
                for (int ks = 0; ks < 8; ++ks) {
                    uint32_t bf[2][2];
                    {
                        const int r = wn * 16 + hr;
                        const int kb = ks * 32 + hk;
                        uint32_t r0, r1, r2, r3;
                        ldm_x4(r0, r1, r2, r3,
                               Bb + (uint32_t)r * 256u + (uint32_t)(kb ^ ((r & 15) << 4)));
                        bf[0][0] = r0; bf[0][1] = r1;
                        bf[1][0] = r2; bf[1][1] = r3;
                    }
                    uint32_t a[2][4];
#pragma unroll
                    for (int mt = 0; mt < 2; ++mt) {
                        const int r = wm * 32 + mt * 16 + gr;
                        const int kb = ks * 32 + gk;
                        ldm_x4(a[mt][0], a[mt][1], a[mt][2], a[mt][3],
                               Ab + (uint32_t)r * 256u + (uint32_t)(kb ^ ((r & 15) << 4)));
                    }
#pragma unroll
                    for (int mt = 0; mt < 2; ++mt)
#pragma unroll
                        for (int nt = 0; nt < 2; ++nt)
                            mma_f16(c[mt][nt], a[mt][0], a[mt][1], a[mt][2], a[mt][3],
                                    bf[nt][0], bf[nt][1]);

                    const int s = ch * 8 + ks;
                    if ((s % 6) == 5) {           // head boundary: fold into hp
                        const int h = s / 6;
                        const float w0 = s_w1[h],       w1v = s_w1[8 + h];
                        const float w2v = s_w1[16 + h], w3  = s_w1[24 + h];
#pragma unroll
                        for (int mt = 0; mt < 2; ++mt)
#pragma unroll
                            for (int nt = 0; nt < 2; ++nt)
#pragma unroll
                                for (int k = 0; k < 4; ++k) {
                                    const float vv = c[mt][nt][k];
                                    hp[mt][nt][k][0] = fmaf(w0,  vv, hp[mt][nt][k][0]);
                                    hp[mt][nt][k][1] = fmaf(w1v, vv, hp[mt][nt][k][1]);
                                    hp[mt][nt][k][2] = fmaf(w2v, vv, hp[mt][nt][k][2]);
                                    hp[mt][nt][k][3] = fmaf(w3,  vv, hp[mt][nt][k][3]);
                                    c[mt][nt][k] = 0.0f;
                                }
                    }
                }
            }

            // Epilogue: GELU(erf) + W2, float2 stores
            const float b10 = s_mi[0], b11 = s_mi[1], b12 = s_mi[2], b13 = s_mi[3];
            const float w20 = s_mi[4], w21 = s_mi[5], w22 = s_mi[6], w23 = s_mi[7];
            const float bb2 = s_mi[8];
            const float inv_sqrt2 = 0.70710678118654752f;
#pragma unroll
            for (int mt = 0; mt < 2; ++mt)
#pragma unroll
                for (int nt = 0; nt < 2; ++nt) {
                    const int col = n0 + wn * 16 + nt * 8 + (lane & 3) * 2;
#pragma unroll
                    for (int h = 0; h < 2; ++h) {
                        const int row = m0 + wm * 32 + mt * 16 + (lane >> 2) + h * 8;
                        float o[2];
#pragma unroll
                        for (int e = 0; e < 2; ++e) {
                            const int k = 2 * h + e;
                            float x0 = hp[mt][nt][k][0] + b10;
                            float x1 = hp[mt][nt][k][1] + b11;
                            float x2 = hp[mt][nt][k][2] + b12;
                            float x3 = hp[mt][nt][k][3] + b13;
                            float g0 = 0.5f * x0 * (1.0f + erff(x0 * inv_sqrt2));
                            float g1 = 0.5f * x1 * (1.0f + erff(x1 * inv_sqrt2));
                            float g2 = 0.5f * x2 * (1.0f + erff(x2 * inv_sqrt2));
                            float g3 = 0.5f * x3 * (1.0f + erff(x3 * inv_sqrt2));
                            float s = bb2;
                            s = fmaf(w20, g0, s); s = fmaf(w21, g1, s);
                            s = fmaf(w22, g2, s); s = fmaf(w23, g3, s);
                            o[e] = s;
                        }
                        *(float2*)(outp + (size_t)row * NTOT + col) = make_float2(o[0], o[1]);
                    }
                }
        }
    }
}

// ---------------------------------------------------------------------------
extern "C" void kernel_launch(void* const* d_in, const int* in_sizes, int n_in,
                              void* d_out, int out_size)
{
    const float* query  = (const float*)d_in[0];
    const float* search = (const float*)d_in[1];
    const float* Wq     = (const float*)d_in[2];
    const float* bq     = (const float*)d_in[3];
    const float* Wk     = (const float*)d_in[4];
    const float* bk     = (const float*)d_in[5];
    const float* W1     = (const float*)d_in[6];
    const float* b1     = (const float*)d_in[7];
    const float* W2     = (const float*)d_in[8];
    const float* b2     = (const float*)d_in[9];
    float* out = (float*)d_out;

    cudaFuncSetAttribute(fused_tc, cudaFuncAttributeMaxDynamicSharedMemorySize, 49536);

    const int total4 = N4S + N4Q + 2 * N4W;
    split_all<<<(total4 + 255) / 256, 256>>>(search, query, Wk, Wq);

    // PDL secondary launch: fused CTAs come up during split's last wave.
    // griddepcontrol.wait inside the kernel enforces correctness; fall back
    // to a plain launch on any error (worst case = R15 behavior).
    cudaLaunchConfig_t cfg = {};
    cfg.gridDim = dim3(444, 1, 1);
    cfg.blockDim = dim3(128, 1, 1);
    cfg.dynamicSmemBytes = 49536;
    cudaLaunchAttribute attrs[1];
    attrs[0].id = cudaLaunchAttributeProgrammaticStreamSerialization;
    attrs[0].val.programmaticStreamSerializationAllowed = 1;
    cfg.attrs = attrs;
    cfg.numAttrs = 1;
    cudaError_t err = cudaLaunchKernelEx(&cfg, fused_tc,
                                         bk, bq, W1, b1, W2, b2, out);
    if (err != cudaSuccess) {
        (void)cudaGetLastError();   // clear sticky error, use plain launch
        fused_tc<<<444, 128, 49536>>>(bk, bq, W1, b1, W2, b2, out);
    }
}